// round 13
// baseline (speedup 1.0000x reference)
#include <cuda_runtime.h>
#include <cuda_bf16.h>
#include <math.h>

// ---------------------------------------------------------------------------
// TrendsGRU: out[t,b,:] = GRU-scan(x) @ Wo + bo
// T=512, B=64, I=512, H=1024, O=512
//
//   0) pack kernels: W (x-part) and Wo -> bf16 hi/lo mma B-fragment arrays
//   1) pre-GEMM  (tensor, hi/lo bf16 3-product): g_gx = x @ [Wz|Wr|Wh]_x + b
//   2) persistent scan: 64 CTAs x 256 thr (no reg cap), each CTA owns 32 zr
//      cols + 16 cand cols; weights in 192KB smem; halved h-broadcast L2
//      traffic; 64-wide flag barrier, 2 barriers/step
//   3) post-GEMM (tensor): out = h_all @ Wo + bo
// ---------------------------------------------------------------------------

#define TT 512
#define BB 64
#define II 512
#define HH 1024
#define OO 512
#define H3 3072
#define TB (TT * BB)
#define NCTA 64
#define STHR 256

// -------------------------- scratch (device globals) -----------------------
__device__ float g_gx[(size_t)TB * H3];           // gate pre-activations (x part + bias)
__device__ float g_h[(size_t)(TT + 1) * BB * HH]; // h_all fp32, slot 0 = zeros
__device__ float g_z[BB * HH];                    // z gate (current step)
__device__ uint2 g_hb[512 * BB];                  // [kpair][b] (hi2,lo2) bf16 of current h
__device__ uint2 g_hrb[512 * BB];                 // [kpair][b] (hi2,lo2) bf16 of h*r
__device__ unsigned g_barCount;                   // init barrier (gen-based)
__device__ unsigned g_barGen;
__device__ unsigned g_flag[NCTA * 8];             // padded per-CTA progress flags

// W fragment arrays (packed once per launch)
__device__ uint4 g_wfz[(II / 16) * (HH / 8) * 32];
__device__ uint4 g_wfr[(II / 16) * (HH / 8) * 32];
__device__ uint4 g_wfh[(II / 16) * (HH / 8) * 32];
__device__ uint4 g_wfo[(HH / 16) * (OO / 8) * 32];

// ---------------------------------------------------------------------------
// common helpers
// ---------------------------------------------------------------------------
__device__ __forceinline__ float sigmoidf_(float v) { return 1.f / (1.f + __expf(-v)); }
__device__ __forceinline__ float2 ldcg2(const float* p) { return __ldcg((const float2*)p); }

__device__ __forceinline__ void hilo2(float a, float b, unsigned& h, unsigned& l)
{
    __nv_bfloat162 hv = __floats2bfloat162_rn(a, b);
    float ra = a - __bfloat162float(hv.x);
    float rb = b - __bfloat162float(hv.y);
    __nv_bfloat162 lv = __floats2bfloat162_rn(ra, rb);
    h = *reinterpret_cast<unsigned*>(&hv);
    l = *reinterpret_cast<unsigned*>(&lv);
}

__device__ __forceinline__ void mma16816(float* d,
                                         unsigned a0, unsigned a1, unsigned a2, unsigned a3,
                                         unsigned b0, unsigned b1)
{
    asm volatile(
        "mma.sync.aligned.m16n8k16.row.col.f32.bf16.bf16.f32 "
        "{%0,%1,%2,%3},{%4,%5,%6,%7},{%8,%9},{%0,%1,%2,%3};"
        : "+f"(d[0]), "+f"(d[1]), "+f"(d[2]), "+f"(d[3])
        : "r"(a0), "r"(a1), "r"(a2), "r"(a3), "r"(b0), "r"(b1));
}

// ---------------------------------------------------------------------------
// pack kernel: W fp32 [K][N] -> B-fragment uint4s
// ---------------------------------------------------------------------------
__global__ void pack_wfrag(const float* __restrict__ W, uint4* __restrict__ out,
                           int K, int N)
{
    int e = blockIdx.x * blockDim.x + threadIdx.x;
    int total = (K / 16) * (N / 8) * 32;
    if (e >= total) return;
    int lane = e & 31;
    int nt = (e >> 5) % (N / 8);
    int ks = (e >> 5) / (N / 8);
    int col = nt * 8 + (lane >> 2);
    int k0 = ks * 16 + (lane & 3) * 2;
    float w0 = __ldg(&W[(size_t)k0 * N + col]);
    float w1 = __ldg(&W[(size_t)(k0 + 1) * N + col]);
    float w8 = __ldg(&W[(size_t)(k0 + 8) * N + col]);
    float w9 = __ldg(&W[(size_t)(k0 + 9) * N + col]);
    unsigned b0h, b0l, b1h, b1l;
    hilo2(w0, w1, b0h, b0l);
    hilo2(w8, w9, b1h, b1l);
    out[e] = make_uint4(b0h, b1h, b0l, b1l);
}

// ---------------------------------------------------------------------------
// Tensor-core GEMM with bias (unchanged from R11)
// ---------------------------------------------------------------------------
__global__ __launch_bounds__(256, 2) void mma_gemm_bias(
    const float* __restrict__ A, const uint4* __restrict__ Wf,
    const float* __restrict__ bias, float* __restrict__ C,
    int K, int lda, int ntilesTot, int ldc)
{
    const int w = threadIdx.x >> 5;
    const int lane = threadIdx.x & 31;
    const int r = lane >> 2, q = lane & 3;
    const int mrow = blockIdx.y * 128 + w * 16 + r;
    const int nt0 = blockIdx.x * 8;

    const float* Arow0 = A + (size_t)mrow * lda + q * 2;
    const float* Arow1 = Arow0 + (size_t)8 * lda;

    float acc[8][4];
#pragma unroll
    for (int n = 0; n < 8; n++)
#pragma unroll
        for (int i = 0; i < 4; i++) acc[n][i] = 0.f;

    const int KS = K / 16;
#pragma unroll 2
    for (int ks = 0; ks < KS; ++ks) {
        float2 a0 = *(const float2*)(Arow0 + ks * 16);
        float2 a1 = *(const float2*)(Arow1 + ks * 16);
        float2 a2 = *(const float2*)(Arow0 + ks * 16 + 8);
        float2 a3 = *(const float2*)(Arow1 + ks * 16 + 8);
        unsigned a0h, a0l, a1h, a1l, a2h, a2l, a3h, a3l;
        hilo2(a0.x, a0.y, a0h, a0l);
        hilo2(a1.x, a1.y, a1h, a1l);
        hilo2(a2.x, a2.y, a2h, a2l);
        hilo2(a3.x, a3.y, a3h, a3l);
        const uint4* bp = Wf + ((size_t)ks * ntilesTot + nt0) * 32 + lane;
#pragma unroll
        for (int nt = 0; nt < 8; ++nt) {
            uint4 B = __ldg(&bp[nt * 32]);
            mma16816(acc[nt], a0h, a1h, a2h, a3h, B.x, B.y);
            mma16816(acc[nt], a0h, a1h, a2h, a3h, B.z, B.w);
            mma16816(acc[nt], a0l, a1l, a2l, a3l, B.x, B.y);
        }
    }

#pragma unroll
    for (int nt = 0; nt < 8; ++nt) {
        int col0 = (nt0 + nt) * 8 + q * 2;
        float2 bb = *(const float2*)&bias[col0];
        *(float2*)&C[(size_t)mrow * ldc + col0] =
            make_float2(acc[nt][0] + bb.x, acc[nt][1] + bb.y);
        *(float2*)&C[(size_t)(mrow + 8) * ldc + col0] =
            make_float2(acc[nt][2] + bb.x, acc[nt][3] + bb.y);
    }
}

// ---------------------------------------------------------------------------
// Persistent GRU scan kernel — 64 CTAs, 256 threads, 2-way K-split
// ---------------------------------------------------------------------------
#define ZRC 32 // zr columns per CTA (2048/64)
#define HCC 16 // candidate columns per CTA (1024/64)
#define NKS 64 // K=1024 -> 64 mma k-steps of 16
#define KG 2   // k-split groups
#define KPG (NKS / KG) // 32 k-steps per warp
#define PD 4   // A-fragment software-pipeline depth

#define WZR_U4 (NKS * 4 * 32) // 8192 uint4 (128KB)
#define WH_U4  (NKS * 2 * 32) // 4096 uint4 (64KB)
#define RED_F  (4 * 32 * 16)  // 2048 floats (8KB)
#define SMEM_SCAN ((WZR_U4 + WH_U4) * 16 + RED_F * 4) // 200KB

__device__ __forceinline__ void grid_barrier_init()
{
    __threadfence();
    __syncthreads();
    if (threadIdx.x == 0) {
        volatile unsigned* genp = &g_barGen;
        unsigned gen = *genp;
        unsigned arrived = atomicAdd(&g_barCount, 1u);
        if (arrived == NCTA - 1) {
            atomicExch(&g_barCount, 0u);
            __threadfence();
            atomicAdd(&g_barGen, 1u);
        } else {
            while (*genp == gen) { __nanosleep(64); }
        }
    }
    __syncthreads();
    __threadfence();
}

__device__ __forceinline__ void flag_barrier(int c, unsigned target)
{
    __threadfence();
    __syncthreads();
    if (threadIdx.x == 0)
        *(volatile unsigned*)&g_flag[c * 8] = target;
    if (threadIdx.x < NCTA) {
        volatile unsigned* fp = &g_flag[threadIdx.x * 8];
        while (*fp < target) { __nanosleep(40); }
    }
    __syncthreads();
    __threadfence();
}

__global__ __launch_bounds__(STHR, 1) void gru_scan(
    const float* __restrict__ Wz, const float* __restrict__ Wr,
    const float* __restrict__ Wh)
{
    extern __shared__ unsigned char smraw[];
    uint4* wzr4 = (uint4*)smraw;         // [kstep][4 nt][lane]
    uint4* wh4  = wzr4 + WZR_U4;         // [kstep][2 nt][lane]
    float* red  = (float*)(wh4 + WH_U4); // [4 w][32 lane][16]

    const int tid = threadIdx.x;
    const int c = blockIdx.x;
    const int warp = tid >> 5;
    const int lane = tid & 31;
    const int g = warp >> 2;  // k-group 0..1
    const int w = warp & 3;   // row-group 0..3
    const int quad = lane & 3;
    const int mrow = w * 16 + (lane >> 2);
    const int q2 = quad * 2;
    const bool isZ = (c < 32);
    const int ksBeg = g * KPG;

    if (tid == 0) *(volatile unsigned*)&g_flag[c * 8] = 0u;

    // ---- prepack recurrent weight slices into SMEM fragment layout (once) ----
    for (int e = tid; e < NKS * 4 * 32; e += STHR) {
        int kst = e >> 7, nt = (e >> 5) & 3, ln = e & 31;
        int jg = c * ZRC + nt * 8 + (ln >> 2);
        int k0 = kst * 16 + (ln & 3) * 2;
        const float* Wsel;
        int col;
        if (jg < HH) { Wsel = Wz; col = jg; }
        else         { Wsel = Wr; col = jg - HH; }
        float w0 = __ldg(&Wsel[(size_t)(II + k0) * HH + col]);
        float w1 = __ldg(&Wsel[(size_t)(II + k0 + 1) * HH + col]);
        float w8 = __ldg(&Wsel[(size_t)(II + k0 + 8) * HH + col]);
        float w9 = __ldg(&Wsel[(size_t)(II + k0 + 9) * HH + col]);
        unsigned b0h, b0l, b1h, b1l;
        hilo2(w0, w1, b0h, b0l);
        hilo2(w8, w9, b1h, b1l);
        wzr4[e] = make_uint4(b0h, b1h, b0l, b1l);
    }
    for (int e = tid; e < NKS * 2 * 32; e += STHR) {
        int kst = e >> 6, nt = (e >> 5) & 1, ln = e & 31;
        int col = c * HCC + nt * 8 + (ln >> 2);
        int k0 = kst * 16 + (ln & 3) * 2;
        float w0 = __ldg(&Wh[(size_t)(II + k0) * HH + col]);
        float w1 = __ldg(&Wh[(size_t)(II + k0 + 1) * HH + col]);
        float w8 = __ldg(&Wh[(size_t)(II + k0 + 8) * HH + col]);
        float w9 = __ldg(&Wh[(size_t)(II + k0 + 9) * HH + col]);
        unsigned b0h, b0l, b1h, b1l;
        hilo2(w0, w1, b0h, b0l);
        hilo2(w8, w9, b1h, b1l);
        wh4[e] = make_uint4(b0h, b1h, b0l, b1l);
    }

    // zero h slot 0 and bf16 h buffer (h0 = 0); redone each launch
    for (int idx = c * STHR + tid; idx < BB * HH; idx += NCTA * STHR) g_h[idx] = 0.f;
    for (int idx = c * STHR + tid; idx < 512 * BB; idx += NCTA * STHR) g_hb[idx] = make_uint2(0u, 0u);
    grid_barrier_init();

    const uint2* hbB  = g_hb  + (size_t)quad * BB + mrow;
    const uint2* hrbB = g_hrb + (size_t)quad * BB + mrow;

#define LOADA(src, ks, j)                                        \
    do {                                                         \
        const uint2* _p = (src) + (size_t)(ks) * (8 * BB);       \
        A0[j] = __ldcg(_p);                                      \
        A1[j] = __ldcg(_p + 8);                                  \
        A2[j] = __ldcg(_p + 4 * BB);                             \
        A3[j] = __ldcg(_p + 4 * BB + 8);                         \
    } while (0)

    unsigned bt = 0;

    for (int t = 0; t < TT; ++t) {
        const float* hprev = g_h + (size_t)t * BB * HH;
        const float* gx = g_gx + (size_t)t * BB * H3;

        // ---------- phase-1 epilogue operand prefetch (g==0 warps only) ----------
        float2 p1gx[4][2], p1hp[4][2];
        if (g == 0) {
#pragma unroll
            for (int nt = 0; nt < 4; ++nt) {
                int jg = c * ZRC + nt * 8 + q2;
                p1gx[nt][0] = ldcg2(&gx[(size_t)mrow * H3 + jg]);
                p1gx[nt][1] = ldcg2(&gx[(size_t)(mrow + 8) * H3 + jg]);
                if (!isZ) {
                    int jr = jg - HH;
                    p1hp[nt][0] = ldcg2(&hprev[(size_t)mrow * HH + jr]);
                    p1hp[nt][1] = ldcg2(&hprev[(size_t)(mrow + 8) * HH + jr]);
                }
            }
        }

        // ================= phase 1: zr = hprev @ Wzr_slice ==================
        float acc1[12][4]; // [nt*3 + {hh,hl,lh}]
#pragma unroll
        for (int gg = 0; gg < 12; gg++)
#pragma unroll
            for (int i = 0; i < 4; i++) acc1[gg][i] = 0.f;

        {
            uint2 A0[PD], A1[PD], A2[PD], A3[PD];
#pragma unroll
            for (int j = 0; j < PD; ++j) LOADA(hbB, ksBeg + j, j);
#pragma unroll 1
            for (int l8 = 0; l8 < KPG; l8 += PD) {
#pragma unroll
                for (int j = 0; j < PD; ++j) {
                    int l = l8 + j, ks = ksBeg + l;
                    uint2 u0 = A0[j], u1 = A1[j], u2 = A2[j], u3 = A3[j];
                    if (l + PD < KPG) LOADA(hbB, ks + PD, j);
#pragma unroll
                    for (int nt = 0; nt < 4; ++nt) {
                        uint4 B = wzr4[(ks * 4 + nt) * 32 + lane];
                        mma16816(acc1[nt * 3 + 0], u0.x, u1.x, u2.x, u3.x, B.x, B.y);
                        mma16816(acc1[nt * 3 + 1], u0.x, u1.x, u2.x, u3.x, B.z, B.w);
                        mma16816(acc1[nt * 3 + 2], u0.y, u1.y, u2.y, u3.y, B.x, B.y);
                    }
                }
            }
        }
        // combine 3 products per nt -> 16 partials; reduce across the 2 k-groups
        float ps[16];
#pragma unroll
        for (int nt = 0; nt < 4; ++nt)
#pragma unroll
            for (int i = 0; i < 4; i++)
                ps[nt * 4 + i] = acc1[nt * 3][i] + acc1[nt * 3 + 1][i] + acc1[nt * 3 + 2][i];
        if (g == 1) {
            float* rp = red + (w * 32 + lane) * 16;
#pragma unroll
            for (int i = 0; i < 16; i++) rp[i] = ps[i];
        }
        __syncthreads();
        if (g == 0) {
            const float* rp = red + (w * 32 + lane) * 16;
#pragma unroll
            for (int i = 0; i < 16; i++) ps[i] += rp[i];
            // epilogue: add gx, sigmoid, publish z or (h*r) in bf16 hi/lo
#pragma unroll
            for (int nt = 0; nt < 4; ++nt) {
                int jg = c * ZRC + nt * 8 + q2;
                float s0 = ps[nt * 4 + 0], s1 = ps[nt * 4 + 1];
                float s2 = ps[nt * 4 + 2], s3 = ps[nt * 4 + 3];
                if (isZ) {
                    float2 zt = make_float2(sigmoidf_(s0 + p1gx[nt][0].x), sigmoidf_(s1 + p1gx[nt][0].y));
                    float2 zb = make_float2(sigmoidf_(s2 + p1gx[nt][1].x), sigmoidf_(s3 + p1gx[nt][1].y));
                    *(float2*)&g_z[mrow * HH + jg] = zt;
                    *(float2*)&g_z[(mrow + 8) * HH + jg] = zb;
                } else {
                    int kp = (jg - HH) >> 1;
                    float r0 = sigmoidf_(s0 + p1gx[nt][0].x), r1 = sigmoidf_(s1 + p1gx[nt][0].y);
                    float r2 = sigmoidf_(s2 + p1gx[nt][1].x), r3 = sigmoidf_(s3 + p1gx[nt][1].y);
                    unsigned hh, ll;
                    hilo2(r0 * p1hp[nt][0].x, r1 * p1hp[nt][0].y, hh, ll);
                    g_hrb[kp * BB + mrow] = make_uint2(hh, ll);
                    hilo2(r2 * p1hp[nt][1].x, r3 * p1hp[nt][1].y, hh, ll);
                    g_hrb[kp * BB + mrow + 8] = make_uint2(hh, ll);
                }
            }
        }
        flag_barrier(c, ++bt);

        // ---------- phase-2 epilogue operand prefetch (g==0 warps only) ----------
        float2 p2gx[2][2], p2z[2][2], p2hp[2][2];
        if (g == 0) {
#pragma unroll
            for (int nt = 0; nt < 2; ++nt) {
                int j = c * HCC + nt * 8 + q2;
                p2gx[nt][0] = ldcg2(&gx[(size_t)mrow * H3 + 2 * HH + j]);
                p2gx[nt][1] = ldcg2(&gx[(size_t)(mrow + 8) * H3 + 2 * HH + j]);
                p2z[nt][0] = ldcg2(&g_z[mrow * HH + j]);
                p2z[nt][1] = ldcg2(&g_z[(mrow + 8) * HH + j]);
                p2hp[nt][0] = ldcg2(&hprev[(size_t)mrow * HH + j]);
                p2hp[nt][1] = ldcg2(&hprev[(size_t)(mrow + 8) * HH + j]);
            }
        }

        // ================= phase 2: cand = (h*r) @ Wh_slice =================
        float acc2[6][4];
#pragma unroll
        for (int gg = 0; gg < 6; gg++)
#pragma unroll
            for (int i = 0; i < 4; i++) acc2[gg][i] = 0.f;

        {
            uint2 A0[PD], A1[PD], A2[PD], A3[PD];
#pragma unroll
            for (int jj = 0; jj < PD; ++jj) LOADA(hrbB, ksBeg + jj, jj);
#pragma unroll 1
            for (int l8 = 0; l8 < KPG; l8 += PD) {
#pragma unroll
                for (int jj = 0; jj < PD; ++jj) {
                    int l = l8 + jj, ks = ksBeg + l;
                    uint2 u0 = A0[jj], u1 = A1[jj], u2 = A2[jj], u3 = A3[jj];
                    if (l + PD < KPG) LOADA(hrbB, ks + PD, jj);
#pragma unroll
                    for (int nt = 0; nt < 2; ++nt) {
                        uint4 B = wh4[(ks * 2 + nt) * 32 + lane];
                        mma16816(acc2[nt * 3 + 0], u0.x, u1.x, u2.x, u3.x, B.x, B.y);
                        mma16816(acc2[nt * 3 + 1], u0.x, u1.x, u2.x, u3.x, B.z, B.w);
                        mma16816(acc2[nt * 3 + 2], u0.y, u1.y, u2.y, u3.y, B.x, B.y);
                    }
                }
            }
        }
        float qs[8];
#pragma unroll
        for (int nt = 0; nt < 2; ++nt)
#pragma unroll
            for (int i = 0; i < 4; i++)
                qs[nt * 4 + i] = acc2[nt * 3][i] + acc2[nt * 3 + 1][i] + acc2[nt * 3 + 2][i];
        if (g == 1) {
            float* rp = red + (w * 32 + lane) * 16;
#pragma unroll
            for (int i = 0; i < 8; i++) rp[i] = qs[i];
        }
        __syncthreads();
        if (g == 0) {
            const float* rp = red + (w * 32 + lane) * 16;
#pragma unroll
            for (int i = 0; i < 8; i++) qs[i] += rp[i];
            // epilogue: h_new = z*h + (1-z)*sigmoid(cand)
            float* hnew = g_h + (size_t)(t + 1) * BB * HH;
#pragma unroll
            for (int nt = 0; nt < 2; ++nt) {
                int j = c * HCC + nt * 8 + q2;
                float c0 = sigmoidf_(qs[nt * 4 + 0] + p2gx[nt][0].x);
                float c1 = sigmoidf_(qs[nt * 4 + 1] + p2gx[nt][0].y);
                float c2 = sigmoidf_(qs[nt * 4 + 2] + p2gx[nt][1].x);
                float c3 = sigmoidf_(qs[nt * 4 + 3] + p2gx[nt][1].y);
                float hn0 = p2z[nt][0].x * p2hp[nt][0].x + (1.f - p2z[nt][0].x) * c0;
                float hn1 = p2z[nt][0].y * p2hp[nt][0].y + (1.f - p2z[nt][0].y) * c1;
                float hn2 = p2z[nt][1].x * p2hp[nt][1].x + (1.f - p2z[nt][1].x) * c2;
                float hn3 = p2z[nt][1].y * p2hp[nt][1].y + (1.f - p2z[nt][1].y) * c3;
                *(float2*)&hnew[(size_t)mrow * HH + j] = make_float2(hn0, hn1);
                *(float2*)&hnew[(size_t)(mrow + 8) * HH + j] = make_float2(hn2, hn3);
                int kp = j >> 1;
                unsigned hh, ll;
                hilo2(hn0, hn1, hh, ll);
                g_hb[kp * BB + mrow] = make_uint2(hh, ll);
                hilo2(hn2, hn3, hh, ll);
                g_hb[kp * BB + mrow + 8] = make_uint2(hh, ll);
            }
        }
        flag_barrier(c, ++bt);
    }
#undef LOADA
}

// ---------------------------------------------------------------------------
extern "C" void kernel_launch(void* const* d_in, const int* in_sizes, int n_in,
                              void* d_out, int out_size)
{
    const float* x  = (const float*)d_in[0];
    const float* Wz = (const float*)d_in[1];
    const float* bz = (const float*)d_in[2];
    const float* Wr = (const float*)d_in[3];
    const float* br = (const float*)d_in[4];
    const float* Wh = (const float*)d_in[5];
    const float* bh = (const float*)d_in[6];
    const float* Wo = (const float*)d_in[7];
    const float* bo = (const float*)d_in[8];
    float* out = (float*)d_out;
    (void)in_sizes; (void)n_in; (void)out_size;

    float *gx = nullptr, *hall = nullptr;
    uint4 *wfz = nullptr, *wfr = nullptr, *wfh = nullptr, *wfo = nullptr;
    cudaGetSymbolAddress((void**)&gx, g_gx);
    cudaGetSymbolAddress((void**)&hall, g_h);
    cudaGetSymbolAddress((void**)&wfz, g_wfz);
    cudaGetSymbolAddress((void**)&wfr, g_wfr);
    cudaGetSymbolAddress((void**)&wfh, g_wfh);
    cudaGetSymbolAddress((void**)&wfo, g_wfo);

    cudaFuncSetAttribute(gru_scan, cudaFuncAttributeMaxDynamicSharedMemorySize, SMEM_SCAN);

    // 0) pack fragments
    int preTot = (II / 16) * (HH / 8) * 32;
    int postTot = (HH / 16) * (OO / 8) * 32;
    pack_wfrag<<<(preTot + 255) / 256, 256>>>(Wz, wfz, II, HH);
    pack_wfrag<<<(preTot + 255) / 256, 256>>>(Wr, wfr, II, HH);
    pack_wfrag<<<(preTot + 255) / 256, 256>>>(Wh, wfh, II, HH);
    pack_wfrag<<<(postTot + 255) / 256, 256>>>(Wo, wfo, HH, OO);

    // 1) pre-GEMMs
    dim3 gpre(HH / 64, TB / 128);
    mma_gemm_bias<<<gpre, 256>>>(x, wfz, bz, gx + 0,      II, II, HH / 8, H3);
    mma_gemm_bias<<<gpre, 256>>>(x, wfr, br, gx + HH,     II, II, HH / 8, H3);
    mma_gemm_bias<<<gpre, 256>>>(x, wfh, bh, gx + 2 * HH, II, II, HH / 8, H3);

    // 2) persistent recurrent scan
    gru_scan<<<NCTA, STHR, SMEM_SCAN>>>(Wz, Wr, Wh);

    // 3) post-GEMM
    dim3 gpost(OO / 64, TB / 128);
    mma_gemm_bias<<<gpost, 256>>>(hall + BB * HH, wfo, bo, out, HH, HH, OO / 8, OO);
}

// round 14
// speedup vs baseline: 1.1427x; 1.1427x over previous
#include <cuda_runtime.h>
#include <cuda_bf16.h>
#include <math.h>

// ---------------------------------------------------------------------------
// TrendsGRU: out[t,b,:] = GRU-scan(x) @ Wo + bo
// T=512, B=64, I=512, H=1024, O=512
//
//   0) pack_all: W (x-part) + Wo -> bf16 hi/lo mma B-fragment arrays (1 launch)
//   1) pre-GEMM  (tensor, hi/lo bf16 3-product): g_gx = x @ [Wz|Wr|Wh]_x + b
//   2) persistent scan (launch #5 for ncu): 128 CTAs x 512 thr, 4-way K-split,
//      release/acquire flag barriers (no MEMBAR.GPU), split mid-step wait
//      (phase-2 GEMM starts after h*r producers only)
//   3) post-GEMM (tensor): out = h_all @ Wo + bo
// ---------------------------------------------------------------------------

#define TT 512
#define BB 64
#define II 512
#define HH 1024
#define OO 512
#define H3 3072
#define TB (TT * BB)
#define NCTA 128
#define STHR 512

// -------------------------- scratch (device globals) -----------------------
__device__ float g_gx[(size_t)TB * H3];           // gate pre-activations (x part + bias)
__device__ float g_h[(size_t)(TT + 1) * BB * HH]; // h_all fp32, slot 0 = zeros
__device__ float g_z[BB * HH];                    // z gate (current step)
__device__ uint2 g_hb[512 * BB];                  // [kpair][b] (hi2,lo2) bf16 of current h
__device__ uint2 g_hrb[512 * BB];                 // [kpair][b] (hi2,lo2) bf16 of h*r
__device__ unsigned g_barCount;                   // init barrier (gen-based)
__device__ unsigned g_barGen;
__device__ unsigned g_flag[NCTA * 8];             // padded per-CTA progress flags

// W fragment arrays (packed once per launch)
__device__ uint4 g_wfz[(II / 16) * (HH / 8) * 32];
__device__ uint4 g_wfr[(II / 16) * (HH / 8) * 32];
__device__ uint4 g_wfh[(II / 16) * (HH / 8) * 32];
__device__ uint4 g_wfo[(HH / 16) * (OO / 8) * 32];

// ---------------------------------------------------------------------------
// common helpers
// ---------------------------------------------------------------------------
__device__ __forceinline__ float sigmoidf_(float v) { return 1.f / (1.f + __expf(-v)); }
__device__ __forceinline__ float2 ldcg2(const float* p) { return __ldcg((const float2*)p); }

__device__ __forceinline__ void st_rel(unsigned* p, unsigned v)
{
    asm volatile("st.release.gpu.u32 [%0], %1;" :: "l"(p), "r"(v) : "memory");
}
__device__ __forceinline__ unsigned ld_acq(unsigned* p)
{
    unsigned v;
    asm volatile("ld.acquire.gpu.u32 %0, [%1];" : "=r"(v) : "l"(p) : "memory");
    return v;
}

__device__ __forceinline__ void hilo2(float a, float b, unsigned& h, unsigned& l)
{
    __nv_bfloat162 hv = __floats2bfloat162_rn(a, b);
    float ra = a - __bfloat162float(hv.x);
    float rb = b - __bfloat162float(hv.y);
    __nv_bfloat162 lv = __floats2bfloat162_rn(ra, rb);
    h = *reinterpret_cast<unsigned*>(&hv);
    l = *reinterpret_cast<unsigned*>(&lv);
}

__device__ __forceinline__ void mma16816(float* d,
                                         unsigned a0, unsigned a1, unsigned a2, unsigned a3,
                                         unsigned b0, unsigned b1)
{
    asm volatile(
        "mma.sync.aligned.m16n8k16.row.col.f32.bf16.bf16.f32 "
        "{%0,%1,%2,%3},{%4,%5,%6,%7},{%8,%9},{%0,%1,%2,%3};"
        : "+f"(d[0]), "+f"(d[1]), "+f"(d[2]), "+f"(d[3])
        : "r"(a0), "r"(a1), "r"(a2), "r"(a3), "r"(b0), "r"(b1));
}

// ---------------------------------------------------------------------------
// pack_all: all four W fragment arrays in ONE launch (keeps scan at launch #5)
// ---------------------------------------------------------------------------
__device__ __forceinline__ void pack_one(const float* __restrict__ W,
                                         uint4* __restrict__ out, int N, int e)
{
    int lane = e & 31;
    int nt = (e >> 5) % (N / 8);
    int ks = (e >> 5) / (N / 8);
    int col = nt * 8 + (lane >> 2);
    int k0 = ks * 16 + (lane & 3) * 2;
    float w0 = __ldg(&W[(size_t)k0 * N + col]);
    float w1 = __ldg(&W[(size_t)(k0 + 1) * N + col]);
    float w8 = __ldg(&W[(size_t)(k0 + 8) * N + col]);
    float w9 = __ldg(&W[(size_t)(k0 + 9) * N + col]);
    unsigned b0h, b0l, b1h, b1l;
    hilo2(w0, w1, b0h, b0l);
    hilo2(w8, w9, b1h, b1l);
    out[e] = make_uint4(b0h, b1h, b0l, b1l);
}

#define PRE_TOT ((II / 16) * (HH / 8) * 32)  // 131072
#define POST_TOT ((HH / 16) * (OO / 8) * 32) // 131072

__global__ void pack_all(const float* __restrict__ Wz, const float* __restrict__ Wr,
                         const float* __restrict__ Wh, const float* __restrict__ Wo)
{
    int e = blockIdx.x * blockDim.x + threadIdx.x;
    if (e < PRE_TOT) { pack_one(Wz, g_wfz, HH, e); return; }
    e -= PRE_TOT;
    if (e < PRE_TOT) { pack_one(Wr, g_wfr, HH, e); return; }
    e -= PRE_TOT;
    if (e < PRE_TOT) { pack_one(Wh, g_wfh, HH, e); return; }
    e -= PRE_TOT;
    if (e < POST_TOT) { pack_one(Wo, g_wfo, OO, e); }
}

__global__ void nop_k() {}

// ---------------------------------------------------------------------------
// Tensor-core GEMM with bias (unchanged from R11)
// ---------------------------------------------------------------------------
__global__ __launch_bounds__(256, 2) void mma_gemm_bias(
    const float* __restrict__ A, const uint4* __restrict__ Wf,
    const float* __restrict__ bias, float* __restrict__ C,
    int K, int lda, int ntilesTot, int ldc)
{
    const int w = threadIdx.x >> 5;
    const int lane = threadIdx.x & 31;
    const int r = lane >> 2, q = lane & 3;
    const int mrow = blockIdx.y * 128 + w * 16 + r;
    const int nt0 = blockIdx.x * 8;

    const float* Arow0 = A + (size_t)mrow * lda + q * 2;
    const float* Arow1 = Arow0 + (size_t)8 * lda;

    float acc[8][4];
#pragma unroll
    for (int n = 0; n < 8; n++)
#pragma unroll
        for (int i = 0; i < 4; i++) acc[n][i] = 0.f;

    const int KS = K / 16;
#pragma unroll 2
    for (int ks = 0; ks < KS; ++ks) {
        float2 a0 = *(const float2*)(Arow0 + ks * 16);
        float2 a1 = *(const float2*)(Arow1 + ks * 16);
        float2 a2 = *(const float2*)(Arow0 + ks * 16 + 8);
        float2 a3 = *(const float2*)(Arow1 + ks * 16 + 8);
        unsigned a0h, a0l, a1h, a1l, a2h, a2l, a3h, a3l;
        hilo2(a0.x, a0.y, a0h, a0l);
        hilo2(a1.x, a1.y, a1h, a1l);
        hilo2(a2.x, a2.y, a2h, a2l);
        hilo2(a3.x, a3.y, a3h, a3l);
        const uint4* bp = Wf + ((size_t)ks * ntilesTot + nt0) * 32 + lane;
#pragma unroll
        for (int nt = 0; nt < 8; ++nt) {
            uint4 B = __ldg(&bp[nt * 32]);
            mma16816(acc[nt], a0h, a1h, a2h, a3h, B.x, B.y);
            mma16816(acc[nt], a0h, a1h, a2h, a3h, B.z, B.w);
            mma16816(acc[nt], a0l, a1l, a2l, a3l, B.x, B.y);
        }
    }

#pragma unroll
    for (int nt = 0; nt < 8; ++nt) {
        int col0 = (nt0 + nt) * 8 + q * 2;
        float2 bb = *(const float2*)&bias[col0];
        *(float2*)&C[(size_t)mrow * ldc + col0] =
            make_float2(acc[nt][0] + bb.x, acc[nt][1] + bb.y);
        *(float2*)&C[(size_t)(mrow + 8) * ldc + col0] =
            make_float2(acc[nt][2] + bb.x, acc[nt][3] + bb.y);
    }
}

// ---------------------------------------------------------------------------
// Persistent GRU scan kernel — 512 threads, 4-way K-split, split-wait barrier
// ---------------------------------------------------------------------------
#define ZRC 16 // zr columns per CTA (2048/128)
#define HCC 8  // candidate columns per CTA (1024/128)
#define NKS 64 // K=1024 -> 64 mma k-steps of 16
#define KG 4   // k-split groups
#define KPG (NKS / KG) // 16 k-steps per warp
#define PD 4   // A-fragment software-pipeline depth

#define WZR_U4 (NKS * 2 * 32) // 4096 uint4 (64KB)
#define WH_U4  (NKS * 32)     // 2048 uint4 (32KB)
#define RED_F  ((KG - 1) * 4 * 32 * 8) // 3072 floats (12KB)
#define SMEM_SCAN ((WZR_U4 + WH_U4) * 16 + RED_F * 4)

__device__ __forceinline__ void grid_barrier_init()
{
    __threadfence();
    __syncthreads();
    if (threadIdx.x == 0) {
        volatile unsigned* genp = &g_barGen;
        unsigned gen = *genp;
        unsigned arrived = atomicAdd(&g_barCount, 1u);
        if (arrived == NCTA - 1) {
            atomicExch(&g_barCount, 0u);
            __threadfence();
            atomicAdd(&g_barGen, 1u);
        } else {
            while (*genp == gen) { __nanosleep(64); }
        }
    }
    __syncthreads();
    __threadfence();
}

__global__ __launch_bounds__(STHR, 1) void gru_scan(
    const float* __restrict__ Wz, const float* __restrict__ Wr,
    const float* __restrict__ Wh)
{
    extern __shared__ unsigned char smraw[];
    uint4* wzr4 = (uint4*)smraw;      // [kstep][nt][lane]
    uint4* wh4  = wzr4 + WZR_U4;      // [kstep][lane]
    float* red  = (float*)(wh4 + WH_U4); // [(KG-1)][4 w][32 lane][8]

    const int tid = threadIdx.x;
    const int c = blockIdx.x;
    const int warp = tid >> 5;
    const int lane = tid & 31;
    const int g = warp >> 2;  // k-group 0..3
    const int w = warp & 3;   // row-group 0..3
    const int quad = lane & 3;
    const int mrow = w * 16 + (lane >> 2);
    const int q2 = quad * 2;
    const bool isZ = (c < 64);
    const int ksBeg = g * KPG;

    if (tid == 0) *(volatile unsigned*)&g_flag[c * 8] = 0u;

    // ---- prepack recurrent weight slices into SMEM fragment layout (once) ----
    for (int e = tid; e < NKS * 2 * 32; e += STHR) {
        int kst = e >> 6, nt = (e >> 5) & 1, ln = e & 31;
        int jg = c * ZRC + nt * 8 + (ln >> 2);
        int k0 = kst * 16 + (ln & 3) * 2;
        const float* Wsel;
        int col;
        if (jg < HH) { Wsel = Wz; col = jg; }
        else         { Wsel = Wr; col = jg - HH; }
        float w0 = __ldg(&Wsel[(size_t)(II + k0) * HH + col]);
        float w1 = __ldg(&Wsel[(size_t)(II + k0 + 1) * HH + col]);
        float w8 = __ldg(&Wsel[(size_t)(II + k0 + 8) * HH + col]);
        float w9 = __ldg(&Wsel[(size_t)(II + k0 + 9) * HH + col]);
        unsigned b0h, b0l, b1h, b1l;
        hilo2(w0, w1, b0h, b0l);
        hilo2(w8, w9, b1h, b1l);
        wzr4[e] = make_uint4(b0h, b1h, b0l, b1l);
    }
    for (int e = tid; e < NKS * 32; e += STHR) {
        int kst = e >> 5, ln = e & 31;
        int col = c * HCC + (ln >> 2);
        int k0 = kst * 16 + (ln & 3) * 2;
        float w0 = __ldg(&Wh[(size_t)(II + k0) * HH + col]);
        float w1 = __ldg(&Wh[(size_t)(II + k0 + 1) * HH + col]);
        float w8 = __ldg(&Wh[(size_t)(II + k0 + 8) * HH + col]);
        float w9 = __ldg(&Wh[(size_t)(II + k0 + 9) * HH + col]);
        unsigned b0h, b0l, b1h, b1l;
        hilo2(w0, w1, b0h, b0l);
        hilo2(w8, w9, b1h, b1l);
        wh4[e] = make_uint4(b0h, b1h, b0l, b1l);
    }

    // zero h slot 0 and bf16 h buffer (h0 = 0); redone each launch
    for (int idx = c * STHR + tid; idx < BB * HH; idx += NCTA * STHR) g_h[idx] = 0.f;
    for (int idx = c * STHR + tid; idx < 512 * BB; idx += NCTA * STHR) g_hb[idx] = make_uint2(0u, 0u);
    grid_barrier_init();

    const uint2* hbB  = g_hb  + (size_t)quad * BB + mrow;
    const uint2* hrbB = g_hrb + (size_t)quad * BB + mrow;

#define LOADA(src, ks, j)                                        \
    do {                                                         \
        const uint2* _p = (src) + (size_t)(ks) * (8 * BB);       \
        A0[j] = __ldcg(_p);                                      \
        A1[j] = __ldcg(_p + 8);                                  \
        A2[j] = __ldcg(_p + 4 * BB);                             \
        A3[j] = __ldcg(_p + 4 * BB + 8);                         \
    } while (0)

    for (int t = 0; t < TT; ++t) {
        const float* hprev = g_h + (size_t)t * BB * HH;
        const float* gx = g_gx + (size_t)t * BB * H3;
        const unsigned t1 = 2 * (unsigned)t + 1;
        const unsigned t2 = 2 * (unsigned)t + 2;

        // ---------- phase-1 epilogue operand prefetch (g==0 warps only) ----------
        float2 p1gx[2][2], p1hp[2][2];
        if (g == 0) {
#pragma unroll
            for (int nt = 0; nt < 2; ++nt) {
                int jg = c * ZRC + nt * 8 + q2;
                p1gx[nt][0] = ldcg2(&gx[(size_t)mrow * H3 + jg]);
                p1gx[nt][1] = ldcg2(&gx[(size_t)(mrow + 8) * H3 + jg]);
                if (!isZ) {
                    int jr = jg - HH;
                    p1hp[nt][0] = ldcg2(&hprev[(size_t)mrow * HH + jr]);
                    p1hp[nt][1] = ldcg2(&hprev[(size_t)(mrow + 8) * HH + jr]);
                }
            }
        }

        // ================= phase 1: zr = hprev @ Wzr_slice ==================
        float acc1[6][4];
#pragma unroll
        for (int gg = 0; gg < 6; gg++)
#pragma unroll
            for (int i = 0; i < 4; i++) acc1[gg][i] = 0.f;

        {
            uint2 A0[PD], A1[PD], A2[PD], A3[PD];
#pragma unroll
            for (int j = 0; j < PD; ++j) LOADA(hbB, ksBeg + j, j);
#pragma unroll 1
            for (int l8 = 0; l8 < KPG; l8 += PD) {
#pragma unroll
                for (int j = 0; j < PD; ++j) {
                    int l = l8 + j, ks = ksBeg + l;
                    uint2 u0 = A0[j], u1 = A1[j], u2 = A2[j], u3 = A3[j];
                    if (l + PD < KPG) LOADA(hbB, ks + PD, j);
                    uint4 B0 = wzr4[(ks * 2 + 0) * 32 + lane];
                    uint4 B1 = wzr4[(ks * 2 + 1) * 32 + lane];
                    mma16816(acc1[0], u0.x, u1.x, u2.x, u3.x, B0.x, B0.y);
                    mma16816(acc1[1], u0.x, u1.x, u2.x, u3.x, B0.z, B0.w);
                    mma16816(acc1[2], u0.y, u1.y, u2.y, u3.y, B0.x, B0.y);
                    mma16816(acc1[3], u0.x, u1.x, u2.x, u3.x, B1.x, B1.y);
                    mma16816(acc1[4], u0.x, u1.x, u2.x, u3.x, B1.z, B1.w);
                    mma16816(acc1[5], u0.y, u1.y, u2.y, u3.y, B1.x, B1.y);
                }
            }
        }
        // combine 3 products per nt -> 8 partial floats; reduce across k-groups
        float ps[8];
#pragma unroll
        for (int nt = 0; nt < 2; ++nt)
#pragma unroll
            for (int i = 0; i < 4; i++)
                ps[nt * 4 + i] = acc1[nt * 3][i] + acc1[nt * 3 + 1][i] + acc1[nt * 3 + 2][i];
        if (g > 0) {
            float* rp = red + (((g - 1) * 4 + w) * 32 + lane) * 8;
#pragma unroll
            for (int i = 0; i < 8; i++) rp[i] = ps[i];
        }
        __syncthreads();
        if (g == 0) {
#pragma unroll
            for (int gg = 0; gg < KG - 1; ++gg) {
                const float* rp = red + ((gg * 4 + w) * 32 + lane) * 8;
#pragma unroll
                for (int i = 0; i < 8; i++) ps[i] += rp[i];
            }
            // epilogue: add gx, sigmoid, publish z or (h*r) in bf16 hi/lo
#pragma unroll
            for (int nt = 0; nt < 2; ++nt) {
                int jg = c * ZRC + nt * 8 + q2;
                float s0 = ps[nt * 4 + 0], s1 = ps[nt * 4 + 1];
                float s2 = ps[nt * 4 + 2], s3 = ps[nt * 4 + 3];
                if (isZ) {
                    float2 zt = make_float2(sigmoidf_(s0 + p1gx[nt][0].x), sigmoidf_(s1 + p1gx[nt][0].y));
                    float2 zb = make_float2(sigmoidf_(s2 + p1gx[nt][1].x), sigmoidf_(s3 + p1gx[nt][1].y));
                    *(float2*)&g_z[mrow * HH + jg] = zt;
                    *(float2*)&g_z[(mrow + 8) * HH + jg] = zb;
                } else {
                    int kp = (jg - HH) >> 1;
                    float r0 = sigmoidf_(s0 + p1gx[nt][0].x), r1 = sigmoidf_(s1 + p1gx[nt][0].y);
                    float r2 = sigmoidf_(s2 + p1gx[nt][1].x), r3 = sigmoidf_(s3 + p1gx[nt][1].y);
                    unsigned hh, ll;
                    hilo2(r0 * p1hp[nt][0].x, r1 * p1hp[nt][0].y, hh, ll);
                    g_hrb[kp * BB + mrow] = make_uint2(hh, ll);
                    hilo2(r2 * p1hp[nt][1].x, r3 * p1hp[nt][1].y, hh, ll);
                    g_hrb[kp * BB + mrow + 8] = make_uint2(hh, ll);
                }
            }
        }
        // ---- publish phase-1; wait ONLY on h*r producers before phase-2 GEMM ----
        __syncthreads();
        if (tid == 0) st_rel(&g_flag[c * 8], t1);
        if (tid < 64) { while (ld_acq(&g_flag[(64 + tid) * 8]) < t1) {} }
        __syncthreads();

        // ---------- phase-2 epilogue operand prefetch (g==0 warps only) ----------
        int j = c * HCC + q2;
        float2 p2gx0, p2gx1, p2hp0, p2hp1;
        if (g == 0) {
            p2gx0 = ldcg2(&gx[(size_t)mrow * H3 + 2 * HH + j]);
            p2gx1 = ldcg2(&gx[(size_t)(mrow + 8) * H3 + 2 * HH + j]);
            p2hp0 = ldcg2(&hprev[(size_t)mrow * HH + j]);
            p2hp1 = ldcg2(&hprev[(size_t)(mrow + 8) * HH + j]);
        }

        // ================= phase 2: cand = (h*r) @ Wh_slice =================
        float acc2[6][4];
#pragma unroll
        for (int gg = 0; gg < 6; gg++)
#pragma unroll
            for (int i = 0; i < 4; i++) acc2[gg][i] = 0.f;

        {
            uint2 A0[PD], A1[PD], A2[PD], A3[PD];
#pragma unroll
            for (int jj = 0; jj < PD; ++jj) LOADA(hrbB, ksBeg + jj, jj);
#pragma unroll 1
            for (int l8 = 0; l8 < KPG; l8 += PD) {
#pragma unroll
                for (int jj = 0; jj < PD; ++jj) {
                    int l = l8 + jj, ks = ksBeg + l;
                    uint2 u0 = A0[jj], u1 = A1[jj], u2 = A2[jj], u3 = A3[jj];
                    if (l + PD < KPG) LOADA(hrbB, ks + PD, jj);
                    uint4 Bw = wh4[ks * 32 + lane];
                    int g0 = (ks & 1) * 3;
                    mma16816(acc2[g0 + 0], u0.x, u1.x, u2.x, u3.x, Bw.x, Bw.y);
                    mma16816(acc2[g0 + 1], u0.x, u1.x, u2.x, u3.x, Bw.z, Bw.w);
                    mma16816(acc2[g0 + 2], u0.y, u1.y, u2.y, u3.y, Bw.x, Bw.y);
                }
            }
        }
        float qs[4];
        qs[0] = qs[1] = qs[2] = qs[3] = 0.f;
#pragma unroll
        for (int gg = 0; gg < 6; gg++)
#pragma unroll
            for (int i = 0; i < 4; i++) qs[i] += acc2[gg][i];
        if (g > 0) {
            float* rp = red + (((g - 1) * 4 + w) * 32 + lane) * 8;
#pragma unroll
            for (int i = 0; i < 4; i++) rp[i] = qs[i];
        }
        // ---- late wait on z producers (overlapped with phase-2 GEMM above) ----
        if (tid < 64) { while (ld_acq(&g_flag[tid * 8]) < t1) {} }
        __syncthreads();
        if (g == 0) {
#pragma unroll
            for (int gg = 0; gg < KG - 1; ++gg) {
                const float* rp = red + ((gg * 4 + w) * 32 + lane) * 8;
#pragma unroll
                for (int i = 0; i < 4; i++) qs[i] += rp[i];
            }
            // z loads (producers guaranteed done by the late wait)
            float2 p2z0 = ldcg2(&g_z[mrow * HH + j]);
            float2 p2z1 = ldcg2(&g_z[(mrow + 8) * HH + j]);
            // epilogue: h_new = z*h + (1-z)*sigmoid(cand)
            float c0 = sigmoidf_(qs[0] + p2gx0.x), c1 = sigmoidf_(qs[1] + p2gx0.y);
            float c2 = sigmoidf_(qs[2] + p2gx1.x), c3 = sigmoidf_(qs[3] + p2gx1.y);
            float hn0 = p2z0.x * p2hp0.x + (1.f - p2z0.x) * c0;
            float hn1 = p2z0.y * p2hp0.y + (1.f - p2z0.y) * c1;
            float hn2 = p2z1.x * p2hp1.x + (1.f - p2z1.x) * c2;
            float hn3 = p2z1.y * p2hp1.y + (1.f - p2z1.y) * c3;
            float* hnew = g_h + (size_t)(t + 1) * BB * HH;
            *(float2*)&hnew[(size_t)mrow * HH + j] = make_float2(hn0, hn1);
            *(float2*)&hnew[(size_t)(mrow + 8) * HH + j] = make_float2(hn2, hn3);
            int kp = j >> 1;
            unsigned hh, ll;
            hilo2(hn0, hn1, hh, ll);
            g_hb[kp * BB + mrow] = make_uint2(hh, ll);
            hilo2(hn2, hn3, hh, ll);
            g_hb[kp * BB + mrow + 8] = make_uint2(hh, ll);
        }
        // ---- publish phase-2; full wait (everyone needs full new h) ----
        __syncthreads();
        if (tid == 0) st_rel(&g_flag[c * 8], t2);
        if (tid < NCTA) { while (ld_acq(&g_flag[tid * 8]) < t2) {} }
        __syncthreads();
    }
#undef LOADA
}

// ---------------------------------------------------------------------------
extern "C" void kernel_launch(void* const* d_in, const int* in_sizes, int n_in,
                              void* d_out, int out_size)
{
    const float* x  = (const float*)d_in[0];
    const float* Wz = (const float*)d_in[1];
    const float* bz = (const float*)d_in[2];
    const float* Wr = (const float*)d_in[3];
    const float* br = (const float*)d_in[4];
    const float* Wh = (const float*)d_in[5];
    const float* bh = (const float*)d_in[6];
    const float* Wo = (const float*)d_in[7];
    const float* bo = (const float*)d_in[8];
    float* out = (float*)d_out;
    (void)in_sizes; (void)n_in; (void)out_size;

    float *gx = nullptr, *hall = nullptr;
    uint4 *wfz = nullptr, *wfr = nullptr, *wfh = nullptr, *wfo = nullptr;
    cudaGetSymbolAddress((void**)&gx, g_gx);
    cudaGetSymbolAddress((void**)&hall, g_h);
    cudaGetSymbolAddress((void**)&wfz, g_wfz);
    cudaGetSymbolAddress((void**)&wfr, g_wfr);
    cudaGetSymbolAddress((void**)&wfh, g_wfh);
    cudaGetSymbolAddress((void**)&wfo, g_wfo);

    cudaFuncSetAttribute(gru_scan, cudaFuncAttributeMaxDynamicSharedMemorySize, SMEM_SCAN);

    // launch 0: pack all fragment arrays
    int packTot = 3 * PRE_TOT + POST_TOT;
    pack_all<<<(packTot + 255) / 256, 256>>>(Wz, Wr, Wh, Wo);

    // launches 1-3: pre-GEMMs
    dim3 gpre(HH / 64, TB / 128);
    mma_gemm_bias<<<gpre, 256>>>(x, wfz, bz, gx + 0,      II, II, HH / 8, H3);
    mma_gemm_bias<<<gpre, 256>>>(x, wfr, br, gx + HH,     II, II, HH / 8, H3);
    mma_gemm_bias<<<gpre, 256>>>(x, wfh, bh, gx + 2 * HH, II, II, HH / 8, H3);

    // launch 4: nop (aligns gru_scan to launch #5 for ncu -s 5 -c 1)
    nop_k<<<1, 32>>>();

    // launch 5: persistent recurrent scan
    gru_scan<<<NCTA, STHR, SMEM_SCAN>>>(Wz, Wr, Wh);

    // launch 6: post-GEMM
    dim3 gpost(OO / 64, TB / 128);
    mma_gemm_bias<<<gpost, 256>>>(hall + BB * HH, wfo, bo, out, HH, HH, OO / 8, OO);
}